// round 3
// baseline (speedup 1.0000x reference)
#include <cuda_runtime.h>
#include <cuda_bf16.h>

#define NUM_POINTS 16
#define IN_CHANNELS 64
#define OUT_CHANNELS 256
#define NUM_STEPS 3

// Accurate fast tanh: t = 1 - 2/(exp(2x)+1), via ex2.approx (~2ulp) + rcp.approx (~1ulp).
// Saturates correctly: x->+inf => ex2->inf => rcp->0 => t=1; x->-inf => ex2->0 => t=-1.
__device__ __forceinline__ float tanh_fast(float x) {
    const float LOG2E_X2 = 2.8853900817779268f;  // 2*log2(e)
    float e, r;
    float z = x * LOG2E_X2;
    asm("ex2.approx.f32 %0, %1;" : "=f"(e) : "f"(z));
    float d = e + 1.0f;
    asm("rcp.approx.f32 %0, %1;" : "=f"(r) : "f"(d));
    return fmaf(-2.0f, r, 1.0f);
}

__device__ __forceinline__ float iterate_g(float x, const float2* __restrict__ lut) {
#pragma unroll
    for (int s = 0; s < NUM_STEPS; s++) {
        float t = tanh_fast(x);
        // (1+t)*8, round half-to-even to match jnp.round
        int pos = __float2int_rn(fmaf(t, 8.0f, 8.0f));
        pos = max(0, min(NUM_POINTS - 1, pos));
        float2 c = lut[pos];           // pre-scaled by 1/NUM_STEPS
        x = fmaf(t, c.y, x + c.x);
    }
    return x;
}

__global__ __launch_bounds__(256) void functional_flow_kernel(
    const float* __restrict__ data,
    const float* __restrict__ angles,
    const float* __restrict__ velo,
    float* __restrict__ out,
    int nrows) {
    __shared__ float2 lut[NUM_POINTS];

    int tid = threadIdx.x;
    int warp = tid >> 5;
    int lane = tid & 31;
    int row = blockIdx.x * (blockDim.x >> 5) + warp;

    // Issue the data load first so it overlaps the LUT init latency.
    const float2* dp = reinterpret_cast<const float2*>(data);
    float2 d = dp[row * (IN_CHANNELS / 2) + lane];

    if (tid < NUM_POINTS) {
        float a = angles[tid];
        float v = velo[tid] * (1.0f / (float)NUM_STEPS);
        lut[tid] = make_float2(v * __cosf(a), v * __sinf(a));
    }
    __syncthreads();

    float s = iterate_g(d.x, lut) + iterate_g(d.y, lut);

    // warp-wide sum over the 64 channels (2 per lane)
#pragma unroll
    for (int off = 16; off > 0; off >>= 1)
        s += __shfl_xor_sync(0xFFFFFFFFu, s, off);

    // broadcast the row sum to all 256 out channels: 8 floats/lane = 2x float4
    float4 v4 = make_float4(s, s, s, s);
    float4* op = reinterpret_cast<float4*>(out + (size_t)row * OUT_CHANNELS);
    op[lane * 2 + 0] = v4;
    op[lane * 2 + 1] = v4;
}

extern "C" void kernel_launch(void* const* d_in, const int* in_sizes, int n_in,
                              void* d_out, int out_size) {
    const float* data   = (const float*)d_in[0];
    const float* angles = (const float*)d_in[1];
    const float* velo   = (const float*)d_in[2];
    float* out = (float*)d_out;

    int nrows = in_sizes[0] / IN_CHANNELS;  // 4096
    int warps_per_block = 256 / 32;         // 8 rows per block
    int blocks = (nrows + warps_per_block - 1) / warps_per_block;  // 512

    functional_flow_kernel<<<blocks, 256>>>(data, angles, velo, out, nrows);
}

// round 5
// speedup vs baseline: 1.0437x; 1.0437x over previous
#include <cuda_runtime.h>
#include <cuda_bf16.h>

#define NUM_POINTS 16
#define IN_CHANNELS 64
#define OUT_CHANNELS 256
#define NUM_STEPS 3

// Accurate fast tanh: t = 1 - 2/(exp(2x)+1), via ex2.approx (~2ulp) + rcp.approx (~1ulp).
// Saturates correctly: x->+inf => ex2->inf => rcp->0 => t=1; x->-inf => ex2->0 => t=-1.
__device__ __forceinline__ float tanh_fast(float x) {
    const float LOG2E_X2 = 2.8853900817779268f;  // 2*log2(e)
    float e, r;
    float z = x * LOG2E_X2;
    asm("ex2.approx.f32 %0, %1;" : "=f"(e) : "f"(z));
    float d = e + 1.0f;
    asm("rcp.approx.f32 %0, %1;" : "=f"(r) : "f"(d));
    return fmaf(-2.0f, r, 1.0f);
}

__device__ __forceinline__ float iterate_g(float x, const float2* __restrict__ lut) {
    // 8+8t is in [0,16]; fmaf(t, 8, 8 + 1.5*2^23) rounds 8+8t to nearest-even
    // integer directly into the low mantissa bits (single rounding).
    const float MAGIC = 12582912.0f + 8.0f;  // 1.5*2^23 + 8
#pragma unroll
    for (int s = 0; s < NUM_STEPS; s++) {
        float t = tanh_fast(x);
        int pos = __float_as_int(fmaf(t, 8.0f, MAGIC)) & 31;
        pos = min(pos, NUM_POINTS - 1);
        float2 c = lut[pos];           // pre-scaled by 1/NUM_STEPS
        x = fmaf(t, c.y, x + c.x);
    }
    return x;
}

__global__ __launch_bounds__(256) void functional_flow_kernel(
    const float* __restrict__ data,
    const float* __restrict__ angles,
    const float* __restrict__ velo,
    float* __restrict__ out,
    int nrows) {
    __shared__ float2 lut[NUM_POINTS];

    int tid = threadIdx.x;
    int warp = tid >> 5;
    int lane = tid & 31;
    int row = blockIdx.x * (blockDim.x >> 5) + warp;

    // Issue the data load first so it overlaps the LUT init latency.
    const float2* dp = reinterpret_cast<const float2*>(data);
    float2 d = dp[row * (IN_CHANNELS / 2) + lane];

    if (tid < NUM_POINTS) {
        float a = angles[tid];
        float v = velo[tid] * (1.0f / (float)NUM_STEPS);
        lut[tid] = make_float2(v * __cosf(a), v * __sinf(a));
    }
    __syncthreads();

    // Two independent chains (ILP=2) over the lane's two channels.
    float s = iterate_g(d.x, lut) + iterate_g(d.y, lut);

    // warp-wide sum over the 64 channels (2 per lane)
#pragma unroll
    for (int off = 16; off > 0; off >>= 1)
        s += __shfl_xor_sync(0xFFFFFFFFu, s, off);

    // broadcast the row sum to all 256 out channels: 8 floats/lane = 2x float4
    float4 v4 = make_float4(s, s, s, s);
    float4* op = reinterpret_cast<float4*>(out + (size_t)row * OUT_CHANNELS);
    op[lane * 2 + 0] = v4;
    op[lane * 2 + 1] = v4;
}

extern "C" void kernel_launch(void* const* d_in, const int* in_sizes, int n_in,
                              void* d_out, int out_size) {
    const float* data   = (const float*)d_in[0];
    const float* angles = (const float*)d_in[1];
    const float* velo   = (const float*)d_in[2];
    float* out = (float*)d_out;

    int nrows = in_sizes[0] / IN_CHANNELS;  // 4096
    int warps_per_block = 256 / 32;         // 8 rows per block
    int blocks = (nrows + warps_per_block - 1) / warps_per_block;  // 512

    functional_flow_kernel<<<blocks, 256>>>(data, angles, velo, out, nrows);
}